// round 3
// baseline (speedup 1.0000x reference)
#include <cuda_runtime.h>
#include <cstdint>

#define NPART   100000
#define NFRAMES 500

// Scratch (no allocation allowed): per-frame keys + integer flip thresholds.
__device__ uint2    g_keys[NFRAMES];
__device__ uint32_t g_thresh[2];

__device__ __forceinline__ uint32_t rotl32(uint32_t x, int r) {
    return __funnelshift_l(x, x, r);  // single SHF
}

// Exact threefry2x32 (20 rounds, 5 key injections) — matches JAX's primitive.
__device__ __forceinline__ void threefry(uint32_t k0, uint32_t k1,
                                         uint32_t x0, uint32_t x1,
                                         uint32_t &o0, uint32_t &o1) {
    uint32_t ks2 = k0 ^ k1 ^ 0x1BD11BDAu;
    x0 += k0; x1 += k1;
#define RND(r) { x0 += x1; x1 = rotl32(x1, r); x1 ^= x0; }
    RND(13) RND(15) RND(26) RND(6)
    x0 += k1;  x1 += ks2 + 1u;
    RND(17) RND(29) RND(16) RND(24)
    x0 += ks2; x1 += k0 + 2u;
    RND(13) RND(15) RND(26) RND(6)
    x0 += k0;  x1 += k1 + 3u;
    RND(17) RND(29) RND(16) RND(24)
    x0 += k1;  x1 += ks2 + 4u;
    RND(13) RND(15) RND(26) RND(6)
    x0 += ks2; x1 += k0 + 5u;
#undef RND
    o0 = x0; o1 = x1;
}

// ceil-threshold: count of integers m with m * 2^-23 < X (exact power-of-two scale).
__device__ __forceinline__ uint32_t thresh_from_prob(float p) {
    float X = p * 8388608.0f;            // exact (exponent shift)
    uint32_t T = (uint32_t)X;            // floor
    if ((float)T < X) T++;               // ceil (strict-< preserved when X integral)
    return T;
}

// jax_threefry_partitionable semantics:
//   split(key, n) (foldlike):  keys[i] = (o0(0,i), o1(0,i))
//   random_bits 32-bit:        bits[j] = o0(hi,lo) ^ o1(hi,lo), counter64 = flat j
__global__ void setup_kernel(const int* __restrict__ seed_ptr) {
    int tid = blockIdx.x * blockDim.x + threadIdx.x;
    long long seed = (long long)(*seed_ptr);
    uint32_t k0 = (uint32_t)(((unsigned long long)seed) >> 32);
    uint32_t k1 = (uint32_t)seed;

    // split(key, 2) foldlike: kp = tf(key,0,0), ks = tf(key,0,1)
    uint32_t kp0, kp1, ks0, ks1;
    threefry(k0, k1, 0u, 0u, kp0, kp1);
    threefry(k0, k1, 0u, 1u, ks0, ks1);

    if (tid < NFRAMES) {
        // split(ks, 500) foldlike: keys[f] = tf(ks, 0, f)
        uint32_t o0, o1;
        threefry(ks0, ks1, 0u, (uint32_t)tid, o0, o1);
        g_keys[tid] = make_uint2(o0, o1);
    }
    if (tid == 0) {
        // p = uniform(kp, ()) * 0.001 ; bits = o0(0,0) ^ o1(0,0) under kp
        uint32_t o0, o1;
        threefry(kp0, kp1, 0u, 0u, o0, o1);
        uint32_t bits = o0 ^ o1;
        float u = __uint_as_float((bits >> 9) | 0x3f800000u) - 1.0f;
        float p = u * 0.001f;
        g_thresh[0] = thresh_from_prob(0.2f);
        g_thresh[1] = thresh_from_prob(p);
    }
}

__global__ void __launch_bounds__(256)
hmm_kernel(const float* __restrict__ initial, float2* __restrict__ out) {
    __shared__ uint2 skeys[NFRAMES];
    for (int i = threadIdx.x; i < NFRAMES; i += blockDim.x)
        skeys[i] = g_keys[i];
    __syncthreads();

    int n = blockIdx.x * blockDim.x + threadIdx.x;
    if (n >= NPART) return;

    const uint32_t t0 = g_thresh[0];   // uniform broadcast, L1-resident
    const uint32_t t1 = g_thresh[1];

    // one-hot -> state bit
    uint32_t s = (initial[2 * n + 1] > 0.5f) ? 1u : 0u;

    float2* optr = out + n;
    const uint32_t n2 = 2u * (uint32_t)n;

#pragma unroll 1
    for (int f = 0; f < NFRAMES; f++) {
        uint2 key = skeys[f];
        uint32_t j = n2 + s;                   // 64-bit counter = (0, j), j < 2^32
        uint32_t o0, o1;
        threefry(key.x, key.y, 0u, j, o0, o1);
        uint32_t m = (o0 ^ o1) >> 9;           // folded 32-bit draw -> 23-bit mantissa
        uint32_t th = s ? t1 : t0;
        s ^= (m < th) ? 1u : 0u;               // flip state on hit
        *optr = make_float2(s ? 0.0f : 1.0f, s ? 1.0f : 0.0f);
        optr += NPART;                         // out[f][n][:]
    }
}

extern "C" void kernel_launch(void* const* d_in, const int* in_sizes, int n_in,
                              void* d_out, int out_size) {
    const float* initial = (const float*)d_in[0];
    const int*   seed    = (const int*)d_in[1];
    float2*      out     = (float2*)d_out;
    (void)in_sizes; (void)n_in; (void)out_size;

    setup_kernel<<<2, 256>>>(seed);
    int blocks = (NPART + 255) / 256;   // 391
    hmm_kernel<<<blocks, 256>>>(initial, out);
}